// round 12
// baseline (speedup 1.0000x reference)
#include <cuda_runtime.h>
#include <cuda_bf16.h>

// ============================================================================
// 2-layer LSTM (B=256, T=512, I=64, H=512) + head on sm_100 base via
// mma.sync.m16n8k16 bf16, 3-term split precision, fp32 accum.
// R12: L2-BW-bound fix. 128 CTAs x 256 thr, merged phases (513 barriers).
// Warp tiles are m64 x n16 (was m32 x n32): each B (h) block is read by
// exactly ONE warp per CTA -> intra-CTA B duplication 2x -> 1x, cutting the
// dominant L2 stream (~102 -> ~51 MB/phase). A dup 4x within CTA is absorbed
// by L1 (__ldg). 2 K-groups x 4 n-warps; partials in 2x2x16KB smem.
// ============================================================================

typedef unsigned u32;

#define NCTA 128
#define NTHR 256
#define NQ0  36     // layer-0 k16 tiles: 32 (h0) + 4 (x)
#define NQ1  64     // layer-1 k16 tiles: 32 (h0 cur) + 32 (h1 prev)
#define SMEM_DYN (16384 * 4)   // 2 outputs x 2 K-groups x 64x64 fp32 = 64KB

// ---------------- device scratch (static) -----------------------------------
__device__ __align__(16) __nv_bfloat16 g_WP0[128 * NQ0 * 512];
__device__ __align__(16) __nv_bfloat16 g_WP1[128 * NQ1 * 512];
__device__ __align__(16) __nv_bfloat16 g_XP[512 * 4 * 32 * 256];
__device__ __align__(16) __nv_bfloat16 g_HB[2 * 2 * 32 * 32 * 256];
__device__ float g_C[2 * 512 * 256];
__device__ float g_h1fin[512 * 256];
__device__ float g_bias[2 * 2048];
__device__ u32 g_barCnt;
__device__ volatile u32 g_barGen;

// ---------------- helpers ---------------------------------------------------
__device__ __forceinline__ void grid_barrier() {
    __syncthreads();
    if (threadIdx.x == 0) {
        u32 gen = g_barGen;
        __threadfence();
        if (atomicAdd(&g_barCnt, 1u) == NCTA - 1u) {
            g_barCnt = 0u;
            __threadfence();
            g_barGen = gen + 1u;
        } else {
            while (g_barGen == gen) { }
        }
        __threadfence();
    }
    __syncthreads();
}

__device__ __forceinline__ float sigm(float x) { return 1.0f / (1.0f + expf(-x)); }

__device__ __forceinline__ void mma4(float* d, uint4 a, u32 b0, u32 b1) {
    asm volatile(
        "mma.sync.aligned.m16n8k16.row.col.f32.bf16.bf16.f32 "
        "{%0,%1,%2,%3}, {%4,%5,%6,%7}, {%8,%9}, {%0,%1,%2,%3};"
        : "+f"(d[0]), "+f"(d[1]), "+f"(d[2]), "+f"(d[3])
        : "r"(a.x), "r"(a.y), "r"(a.z), "r"(a.w), "r"(b0), "r"(b1));
}

// One contiguous K segment of NQ k16-steps for an m64 x n16 warp tile.
// A0..A3: lane-adjusted A block ptrs for the four m16 tiles (+64 uint4/q).
// Bp: lane-adjusted B ptr; the warp's two n8 blocks are Bp and Bp+32
// (+1024 uint4 per q). acc[mt][ni][4]; 24 HMMA per q.
template <int NQ>
__device__ __forceinline__ void gemm_seg(
    const uint4* __restrict__ A0p, const uint4* __restrict__ A1p,
    const uint4* __restrict__ A2p, const uint4* __restrict__ A3p,
    const uint4* __restrict__ Bp, float acc[4][2][4])
{
#pragma unroll 2
    for (int q = 0; q < NQ; q++) {
        uint4 b0 = __ldcg(Bp);
        uint4 b1 = __ldcg(Bp + 32);
        uint4 ah0 = __ldg(A0p); uint4 al0 = __ldg(A0p + 1);
        uint4 ah1 = __ldg(A1p); uint4 al1 = __ldg(A1p + 1);
        uint4 ah2 = __ldg(A2p); uint4 al2 = __ldg(A2p + 1);
        uint4 ah3 = __ldg(A3p); uint4 al3 = __ldg(A3p + 1);
        // 3-term split x 4m x 2n = 24 HMMA
        mma4(acc[0][0], ah0, b0.x, b0.y);
        mma4(acc[0][0], ah0, b0.z, b0.w);
        mma4(acc[0][0], al0, b0.x, b0.y);
        mma4(acc[0][1], ah0, b1.x, b1.y);
        mma4(acc[0][1], ah0, b1.z, b1.w);
        mma4(acc[0][1], al0, b1.x, b1.y);
        mma4(acc[1][0], ah1, b0.x, b0.y);
        mma4(acc[1][0], ah1, b0.z, b0.w);
        mma4(acc[1][0], al1, b0.x, b0.y);
        mma4(acc[1][1], ah1, b1.x, b1.y);
        mma4(acc[1][1], ah1, b1.z, b1.w);
        mma4(acc[1][1], al1, b1.x, b1.y);
        mma4(acc[2][0], ah2, b0.x, b0.y);
        mma4(acc[2][0], ah2, b0.z, b0.w);
        mma4(acc[2][0], al2, b0.x, b0.y);
        mma4(acc[2][1], ah2, b1.x, b1.y);
        mma4(acc[2][1], ah2, b1.z, b1.w);
        mma4(acc[2][1], al2, b1.x, b1.y);
        mma4(acc[3][0], ah3, b0.x, b0.y);
        mma4(acc[3][0], ah3, b0.z, b0.w);
        mma4(acc[3][0], al3, b0.x, b0.y);
        mma4(acc[3][1], ah3, b1.x, b1.y);
        mma4(acc[3][1], ah3, b1.z, b1.w);
        mma4(acc[3][1], al3, b1.x, b1.y);
        A0p += 64; A1p += 64; A2p += 64; A3p += 64; Bp += 1024;
    }
}

// Store one warp's partial D tile (m64 x n16) into its gsm region.
__device__ __forceinline__ void store_partials(
    float acc[4][2][4], float* gout, int wn, int lane)
{
#pragma unroll
    for (int mt = 0; mt < 4; mt++)
#pragma unroll
        for (int ni = 0; ni < 2; ni++) {
            int lr = mt * 16 + (lane >> 2);
            int cl = (wn * 2 + ni) * 8 + (lane & 3) * 2;
            float* d = acc[mt][ni];
            *(float2*)&gout[lr * 64 + cl]       = make_float2(d[0], d[1]);
            *(float2*)&gout[(lr + 8) * 64 + cl] = make_float2(d[2], d[3]);
        }
}

// Cell update for one layer from a gsm output region (two K-group partials).
__device__ __forceinline__ void cell_upd(
    const float* gbase, int lay, int pwv, int m_cta, int n_cta,
    int tid, bool fin)
{
    float* Cp = g_C + lay * 131072;
    const float* bp = g_bias + lay * 2048;
#pragma unroll
    for (int e = 0; e < 4; e++) {
        int cell = e * NTHR + tid;
        int jl = cell >> 6, bl = cell & 63;
        int j = m_cta * 16 + jl;
        int b = n_cta * 64 + bl;
        float iv = gbase[(jl * 4 + 0) * 64 + bl] + gbase[4096 + (jl * 4 + 0) * 64 + bl]
                 + __ldg(bp + 0 * 512 + j);
        float fv = gbase[(jl * 4 + 1) * 64 + bl] + gbase[4096 + (jl * 4 + 1) * 64 + bl]
                 + __ldg(bp + 1 * 512 + j);
        float gv = gbase[(jl * 4 + 2) * 64 + bl] + gbase[4096 + (jl * 4 + 2) * 64 + bl]
                 + __ldg(bp + 2 * 512 + j);
        float ov = gbase[(jl * 4 + 3) * 64 + bl] + gbase[4096 + (jl * 4 + 3) * 64 + bl]
                 + __ldg(bp + 3 * 512 + j);
        float c = Cp[j * 256 + b];
        c = sigm(fv) * c + sigm(iv) * tanhf(gv);
        Cp[j * 256 + b] = c;
        float hv = sigm(ov) * tanhf(c);
        __nv_bfloat16 hh = __float2bfloat16_rn(hv);
        __nv_bfloat16 hl = __float2bfloat16_rn(hv - __bfloat162float(hh));
        int n8 = n_cta * 8 + (bl >> 3), nl = bl & 7;
        int lane2 = nl * 4 + ((jl & 7) >> 1);
        int r = jl >> 3, hb = jl & 1;
        int blk = ((pwv * 2 + lay) * 32 + m_cta) * 32 + n8;
        __nv_bfloat16* p = g_HB + blk * 256 + lane2 * 8 + r * 2 + hb;
        p[0] = hh;
        p[4] = hl;
        if (fin) g_h1fin[j * 256 + b] = hv;
    }
}

// ---------------- the persistent kernel -------------------------------------
extern __shared__ __align__(16) float gsm[];   // [out 2][grp 2][64*64]

__global__ void __launch_bounds__(NTHR, 1) lstm_all(
    const float* __restrict__ x,
    const float* __restrict__ Wih0, const float* __restrict__ Whh0,
    const float* __restrict__ bih0, const float* __restrict__ bhh0,
    const float* __restrict__ Wih1, const float* __restrict__ Whh1,
    const float* __restrict__ bih1, const float* __restrict__ bhh1,
    const float* __restrict__ Wout, const float* __restrict__ bout,
    float* __restrict__ out)
{
    const int tid  = threadIdx.x;
    const int wid  = tid >> 5;
    const int lane = tid & 31;
    const int gtid = blockIdx.x * NTHR + tid;
    const int NT   = NCTA * NTHR;

    // ======== prep: identical math/layouts to R10 winner ========
    for (int i = gtid; i < 128 * NQ0 * 512; i += NT) {
        int bi = i >> 9, off = i & 511;
        int l = off >> 4, rem = off & 15;
        int sect = rem >> 3, r = (rem >> 1) & 3, h = rem & 1;
        int mt = bi / NQ0, q = bi % NQ0;
        int lr = (l >> 2) + (r & 1) * 8;
        int c  = (l & 3) * 2 + h + (r >> 1) * 8;
        int R  = mt * 16 + lr;
        int GR = (R & 3) * 512 + (R >> 2);
        int k  = q * 16 + c;
        float w = (k < 512) ? Whh0[GR * 512 + k] : Wih0[GR * 64 + (k - 512)];
        __nv_bfloat16 hh = __float2bfloat16_rn(w);
        g_WP0[i] = sect ? __float2bfloat16_rn(w - __bfloat162float(hh)) : hh;
    }
    for (int i = gtid; i < 128 * NQ1 * 512; i += NT) {
        int bi = i >> 9, off = i & 511;
        int l = off >> 4, rem = off & 15;
        int sect = rem >> 3, r = (rem >> 1) & 3, h = rem & 1;
        int mt = bi / NQ1, q = bi % NQ1;
        int lr = (l >> 2) + (r & 1) * 8;
        int c  = (l & 3) * 2 + h + (r >> 1) * 8;
        int R  = mt * 16 + lr;
        int GR = (R & 3) * 512 + (R >> 2);
        int k  = q * 16 + c;
        float w = (k < 512) ? Wih1[GR * 512 + k] : Whh1[GR * 512 + (k - 512)];
        __nv_bfloat16 hh = __float2bfloat16_rn(w);
        g_WP1[i] = sect ? __float2bfloat16_rn(w - __bfloat162float(hh)) : hh;
    }
    for (int i = gtid; i < 512 * 4 * 32 * 256; i += NT) {
        int bi = i >> 8, off = i & 255;
        int l = off >> 3, rem = off & 7;
        int sect = rem >> 2, r = (rem >> 1) & 1, h = rem & 1;
        int n8 = bi & 31, rest = bi >> 5;
        int qp = rest & 3, t = rest >> 2;
        int kl = r * 8 + (l & 3) * 2 + h;
        int nl = l >> 2;
        int b  = n8 * 8 + nl, ii = qp * 16 + kl;
        float v = x[(b * 512 + t) * 64 + ii];
        __nv_bfloat16 hh = __float2bfloat16_rn(v);
        g_XP[i] = sect ? __float2bfloat16_rn(v - __bfloat162float(hh)) : hh;
    }
    for (int i = gtid; i < 2 * 2 * 32 * 32 * 256; i += NT)
        g_HB[i] = __float2bfloat16(0.f);
    for (int i = gtid; i < 2 * 512 * 256; i += NT) g_C[i] = 0.f;
    for (int i = gtid; i < 2048; i += NT) {
        g_bias[i]        = bih0[i] + bhh0[i];
        g_bias[2048 + i] = bih1[i] + bhh1[i];
    }

    grid_barrier();

    // ======== merged mainloop: phase t = { L1(t-1), L0(t) } ========
    const int m_cta = blockIdx.x >> 2;
    const int n_cta = blockIdx.x & 3;
    const int grp = wid >> 2;              // K-half group
    const int wn  = wid & 3;               // n16 slot (2 n8 blocks)
    const int mt0 = m_cta * 4;             // warp covers all 4 m16 tiles
    const int n8b = n_cta * 8 + wn * 2;

    const uint4* WP0v = (const uint4*)g_WP0;
    const uint4* WP1v = (const uint4*)g_WP1;
    const uint4* XPv  = (const uint4*)g_XP;
    const uint4* HBv  = (const uint4*)g_HB;
    float* gout0 = gsm + grp * 4096;          // L1(t-1) partials
    float* gout1 = gsm + 8192 + grp * 4096;   // L0(t)   partials

    for (int t = 0; t <= 512; t++) {
        const int u = t & 1, v = u ^ 1;
        const bool do1 = (t >= 1);
        const bool do0 = (t <= 511);

        if (do1) {
            // L1(t-1): q0-31 = h0(t-1)@(v,0), q32-63 = h1(t-2)@(u,1)
            float acc[4][2][4] = {};
            const uint4* A0 = WP1v + ((mt0 + 0) * NQ1) * 64 + lane * 2;
            const uint4* A1 = WP1v + ((mt0 + 1) * NQ1) * 64 + lane * 2;
            const uint4* A2 = WP1v + ((mt0 + 2) * NQ1) * 64 + lane * 2;
            const uint4* A3 = WP1v + ((mt0 + 3) * NQ1) * 64 + lane * 2;
            if (grp == 0) {
                gemm_seg<32>(A0, A1, A2, A3,
                             HBv + ((v * 2 + 0) * 1024 + n8b) * 32 + lane, acc);
            } else {
                gemm_seg<32>(A0 + 32 * 64, A1 + 32 * 64, A2 + 32 * 64, A3 + 32 * 64,
                             HBv + ((u * 2 + 1) * 1024 + n8b) * 32 + lane, acc);
            }
            store_partials(acc, gout0, wn, lane);
        }
        if (do0) {
            // L0(t): q0-31 = h0(t-1)@(v,0), q32-35 = x(t)
            float acc[4][2][4] = {};
            const uint4* A0 = WP0v + ((mt0 + 0) * NQ0) * 64 + lane * 2;
            const uint4* A1 = WP0v + ((mt0 + 1) * NQ0) * 64 + lane * 2;
            const uint4* A2 = WP0v + ((mt0 + 2) * NQ0) * 64 + lane * 2;
            const uint4* A3 = WP0v + ((mt0 + 3) * NQ0) * 64 + lane * 2;
            const uint4* Bh = HBv + ((v * 2 + 0) * 1024 + n8b) * 32 + lane;
            if (grp == 0) {
                gemm_seg<18>(A0, A1, A2, A3, Bh, acc);
            } else {
                gemm_seg<14>(A0 + 18 * 64, A1 + 18 * 64, A2 + 18 * 64, A3 + 18 * 64,
                             Bh + 18 * 1024, acc);
                gemm_seg<4>(A0 + 32 * 64, A1 + 32 * 64, A2 + 32 * 64, A3 + 32 * 64,
                            XPv + (t * 4 * 32 + n8b) * 32 + lane, acc);
            }
            store_partials(acc, gout1, wn, lane);
        }
        __syncthreads();

        if (do1) cell_upd(gsm,        1, v, m_cta, n_cta, tid, t == 512);
        if (do0) cell_upd(gsm + 8192, 0, u, m_cta, n_cta, tid, false);

        grid_barrier();
    }

    // ======== head ========
    if (blockIdx.x == 0) {
        int b = tid;
        float a = __ldg(bout);
#pragma unroll 8
        for (int j = 0; j < 512; j++)
            a += fmaxf(__ldcg(g_h1fin + j * 256 + b), 0.f) * __ldg(Wout + j);
        out[b] = a;
    }
}

// ---------------- launch ----------------------------------------------------
extern "C" void kernel_launch(void* const* d_in, const int* in_sizes, int n_in,
                              void* d_out, int out_size) {
    (void)in_sizes; (void)n_in; (void)out_size;
    const float* x    = (const float*)d_in[0];
    const float* Wih0 = (const float*)d_in[1];
    const float* Whh0 = (const float*)d_in[2];
    const float* bih0 = (const float*)d_in[3];
    const float* bhh0 = (const float*)d_in[4];
    const float* Wih1 = (const float*)d_in[5];
    const float* Whh1 = (const float*)d_in[6];
    const float* bih1 = (const float*)d_in[7];
    const float* bhh1 = (const float*)d_in[8];
    const float* Wout = (const float*)d_in[9];
    const float* bout = (const float*)d_in[10];
    float* out = (float*)d_out;

    cudaFuncSetAttribute(lstm_all, cudaFuncAttributeMaxDynamicSharedMemorySize, SMEM_DYN);
    lstm_all<<<NCTA, NTHR, SMEM_DYN>>>(x, Wih0, Whh0, bih0, bhh0,
                                       Wih1, Whh1, bih1, bhh1, Wout, bout, out);
}

// round 13
// speedup vs baseline: 1.5356x; 1.5356x over previous
#include <cuda_runtime.h>
#include <cuda_fp16.h>

// ============================================================================
// 2-layer LSTM (B=256, T=512, I=64, H=512) + head on sm_100 base via
// mma.sync.m16n8k16 fp16, 2-term split (Ahi*B + Alo*B; A split is exact to
// 2^-24, B single fp16 -> per-step gate err ~4e-5), fp32 accum.
// R13: derived from the R10 winner (256 thr, 2 K-groups, m32xn32 warp tiles,
// unroll 4, merged phases L1(t-1)+L0(t), 513 grid barriers). Work per gate
// drops: 24 -> 16 HMMA per q-tile per warp, 8 -> 6 LDG.128 per q (B blocks
// are half-size: 256B per (q,n8)). h writeback is one fp16 store.
// ============================================================================

typedef unsigned u32;

#define NCTA 128
#define NTHR 256
#define NQ0  36     // layer-0 k16 tiles: 32 (h0) + 4 (x)
#define NQ1  64     // layer-1 k16 tiles: 32 (h0 cur) + 32 (h1 prev)
#define SMEM_DYN (16384 * 4)   // 2 outputs x 2 K-groups x 64x64 fp32 = 64KB

// ---------------- device scratch (static) -----------------------------------
// A blocks: 1KB per (mt, q): lane 32B = [a0..a3 hi | a0..a3 lo] (fp16)
__device__ __align__(16) __half g_WP0[128 * NQ0 * 512];
__device__ __align__(16) __half g_WP1[128 * NQ1 * 512];
// B blocks: 512B per (q-tile, n16): lane 16B = [n8a reg0, n8a reg1, n8b reg0, n8b reg1]
__device__ __align__(16) __half g_XP[512 * 4 * 16 * 256];
// h blocks: [parity][layer][q 0..31][n16 0..15] 512B blocks
__device__ __align__(16) __half g_HB[2 * 2 * 32 * 16 * 256];
__device__ float g_C[2 * 512 * 256];
__device__ float g_h1fin[512 * 256];
__device__ float g_bias[2 * 2048];
__device__ u32 g_barCnt;
__device__ volatile u32 g_barGen;

// ---------------- helpers ---------------------------------------------------
__device__ __forceinline__ void grid_barrier() {
    __syncthreads();
    if (threadIdx.x == 0) {
        u32 gen = g_barGen;
        __threadfence();
        if (atomicAdd(&g_barCnt, 1u) == NCTA - 1u) {
            g_barCnt = 0u;
            __threadfence();
            g_barGen = gen + 1u;
        } else {
            while (g_barGen == gen) { }
        }
        __threadfence();
    }
    __syncthreads();
}

__device__ __forceinline__ float sigm(float x) { return 1.0f / (1.0f + expf(-x)); }

__device__ __forceinline__ void mma4(float* d, uint4 a, u32 b0, u32 b1) {
    asm volatile(
        "mma.sync.aligned.m16n8k16.row.col.f32.f16.f16.f32 "
        "{%0,%1,%2,%3}, {%4,%5,%6,%7}, {%8,%9}, {%0,%1,%2,%3};"
        : "+f"(d[0]), "+f"(d[1]), "+f"(d[2]), "+f"(d[3])
        : "r"(a.x), "r"(a.y), "r"(a.z), "r"(a.w), "r"(b0), "r"(b1));
}

// One contiguous K segment of NQ k16-steps for an m32 x n32 warp tile.
// A0p/A1p: lane-adjusted A block ptrs (+64 uint4/q). Bp: lane-adjusted B
// ptr; warp's two n16 blocks are Bp and Bp+32 (+512 uint4 per q).
// 2-term split x 2m x 4n8 = 16 HMMA per q, 6 LDG.128.
template <int NQ>
__device__ __forceinline__ void gemm_seg(
    const uint4* __restrict__ A0p, const uint4* __restrict__ A1p,
    const uint4* __restrict__ Bp, float acc[2][4][4])
{
#pragma unroll 4
    for (int q = 0; q < NQ; q++) {
        uint4 b0  = __ldcg(Bp);        // n8 pair 0,1 (this n16)
        uint4 b1  = __ldcg(Bp + 32);   // n8 pair 2,3 (next n16)
        uint4 ah0 = __ldg(A0p);  uint4 al0 = __ldg(A0p + 1);
        uint4 ah1 = __ldg(A1p);  uint4 al1 = __ldg(A1p + 1);
        mma4(acc[0][0], ah0, b0.x, b0.y);
        mma4(acc[0][0], al0, b0.x, b0.y);
        mma4(acc[0][1], ah0, b0.z, b0.w);
        mma4(acc[0][1], al0, b0.z, b0.w);
        mma4(acc[0][2], ah0, b1.x, b1.y);
        mma4(acc[0][2], al0, b1.x, b1.y);
        mma4(acc[0][3], ah0, b1.z, b1.w);
        mma4(acc[0][3], al0, b1.z, b1.w);
        mma4(acc[1][0], ah1, b0.x, b0.y);
        mma4(acc[1][0], al1, b0.x, b0.y);
        mma4(acc[1][1], ah1, b0.z, b0.w);
        mma4(acc[1][1], al1, b0.z, b0.w);
        mma4(acc[1][2], ah1, b1.x, b1.y);
        mma4(acc[1][2], al1, b1.x, b1.y);
        mma4(acc[1][3], ah1, b1.z, b1.w);
        mma4(acc[1][3], al1, b1.z, b1.w);
        A0p += 64; A1p += 64; Bp += 512;
    }
}

// Store one warp's partial D tile (m32 x n32) into a gsm region.
__device__ __forceinline__ void store_partials(
    float acc[2][4][4], float* gout, int wm, int wn, int lane)
{
#pragma unroll
    for (int mi = 0; mi < 2; mi++)
#pragma unroll
        for (int ni = 0; ni < 4; ni++) {
            int lr = (wm * 2 + mi) * 16 + (lane >> 2);
            int cl = (wn * 4 + ni) * 8 + (lane & 3) * 2;
            float* d = acc[mi][ni];
            *(float2*)&gout[lr * 64 + cl]       = make_float2(d[0], d[1]);
            *(float2*)&gout[(lr + 8) * 64 + cl] = make_float2(d[2], d[3]);
        }
}

// Cell update for one layer from a gsm output region (two K-group partials).
// h writeback: single fp16 into the B-fragment-packed g_HB.
__device__ __forceinline__ void cell_upd(
    const float* gbase, int lay, int pwv, int m_cta, int n_cta,
    int tid, bool fin)
{
    float* Cp = g_C + lay * 131072;
    const float* bp = g_bias + lay * 2048;
#pragma unroll
    for (int e = 0; e < 4; e++) {
        int cell = e * NTHR + tid;
        int jl = cell >> 6, bl = cell & 63;
        int j = m_cta * 16 + jl;
        int b = n_cta * 64 + bl;
        float iv = gbase[(jl * 4 + 0) * 64 + bl] + gbase[4096 + (jl * 4 + 0) * 64 + bl]
                 + __ldg(bp + 0 * 512 + j);
        float fv = gbase[(jl * 4 + 1) * 64 + bl] + gbase[4096 + (jl * 4 + 1) * 64 + bl]
                 + __ldg(bp + 1 * 512 + j);
        float gv = gbase[(jl * 4 + 2) * 64 + bl] + gbase[4096 + (jl * 4 + 2) * 64 + bl]
                 + __ldg(bp + 2 * 512 + j);
        float ov = gbase[(jl * 4 + 3) * 64 + bl] + gbase[4096 + (jl * 4 + 3) * 64 + bl]
                 + __ldg(bp + 3 * 512 + j);
        float c = Cp[j * 256 + b];
        c = sigm(fv) * c + sigm(iv) * tanhf(gv);
        Cp[j * 256 + b] = c;
        float hv = sigm(ov) * tanhf(c);
        // fp16 B-fragment scatter: q = m_cta, kl = jl
        int r  = jl >> 3, tg = (jl >> 1) & 3, hb = jl & 1;
        int nl = bl & 7;
        int n8 = n_cta * 8 + (bl >> 3);
        int p  = n8 & 1, n16 = n8 >> 1;
        int l2 = nl * 4 + tg;
        int blk = ((pwv * 2 + lay) * 32 + m_cta) * 16 + n16;
        g_HB[blk * 256 + l2 * 8 + p * 4 + r * 2 + hb] = __float2half(hv);
        if (fin) g_h1fin[j * 256 + b] = hv;
    }
}

// ---------------- the persistent kernel -------------------------------------
extern __shared__ __align__(16) float gsm[];   // [out 2][grp 2][64*64]

__global__ void __launch_bounds__(NTHR, 1) lstm_all(
    const float* __restrict__ x,
    const float* __restrict__ Wih0, const float* __restrict__ Whh0,
    const float* __restrict__ bih0, const float* __restrict__ bhh0,
    const float* __restrict__ Wih1, const float* __restrict__ Whh1,
    const float* __restrict__ bih1, const float* __restrict__ bhh1,
    const float* __restrict__ Wout, const float* __restrict__ bout,
    float* __restrict__ out)
{
    const int tid  = threadIdx.x;
    const int wid  = tid >> 5;
    const int lane = tid & 31;
    const int gtid = blockIdx.x * NTHR + tid;
    const int NT   = NCTA * NTHR;

    // ======== prep: pack W (fp16 hi/lo) and x (fp16) in fragment order ======
    for (int i = gtid; i < 128 * NQ0 * 512; i += NT) {
        int bi = i >> 9, off = i & 511;
        int l = off >> 4, rem = off & 15;
        int sect = rem >> 3, r = (rem >> 1) & 3, h = rem & 1;
        int mt = bi / NQ0, q = bi % NQ0;
        int lr = (l >> 2) + (r & 1) * 8;
        int c  = (l & 3) * 2 + h + (r >> 1) * 8;
        int R  = mt * 16 + lr;                       // permuted row = j*4+g
        int GR = (R & 3) * 512 + (R >> 2);           // original gate row
        int k  = q * 16 + c;
        float w = (k < 512) ? Whh0[GR * 512 + k] : Wih0[GR * 64 + (k - 512)];
        __half hh = __float2half(w);
        g_WP0[i] = sect ? __float2half(w - __half2float(hh)) : hh;
    }
    for (int i = gtid; i < 128 * NQ1 * 512; i += NT) {
        int bi = i >> 9, off = i & 511;
        int l = off >> 4, rem = off & 15;
        int sect = rem >> 3, r = (rem >> 1) & 3, h = rem & 1;
        int mt = bi / NQ1, q = bi % NQ1;
        int lr = (l >> 2) + (r & 1) * 8;
        int c  = (l & 3) * 2 + h + (r >> 1) * 8;
        int R  = mt * 16 + lr;
        int GR = (R & 3) * 512 + (R >> 2);
        int k  = q * 16 + c;
        float w = (k < 512) ? Wih1[GR * 512 + k] : Whh1[GR * 512 + (k - 512)];
        __half hh = __float2half(w);
        g_WP1[i] = sect ? __float2half(w - __half2float(hh)) : hh;
    }
    // XP: block ((t*4 + qp)*16 + n16); elem l*8 + p*4 + r*2 + h (fp16)
    for (int i = gtid; i < 512 * 4 * 16 * 256; i += NT) {
        int bi = i >> 8, off = i & 255;
        int l = off >> 3, rem = off & 7;
        int p = rem >> 2, r = (rem >> 1) & 1, h = rem & 1;
        int n16 = bi & 15, rest = bi >> 4;
        int qp = rest & 3, t = rest >> 2;
        int n8 = n16 * 2 + p;
        int b  = n8 * 8 + (l >> 2);
        int kk = r * 8 + (l & 3) * 2 + h;
        int ii = qp * 16 + kk;
        g_XP[i] = __float2half(x[(b * 512 + t) * 64 + ii]);
    }
    for (int i = gtid; i < 2 * 2 * 32 * 16 * 256; i += NT)
        g_HB[i] = __float2half(0.f);
    for (int i = gtid; i < 2 * 512 * 256; i += NT) g_C[i] = 0.f;
    for (int i = gtid; i < 2048; i += NT) {
        g_bias[i]        = bih0[i] + bhh0[i];
        g_bias[2048 + i] = bih1[i] + bhh1[i];
    }

    grid_barrier();

    // ======== merged mainloop: phase t = { L1(t-1), L0(t) } ========
    const int m_cta = blockIdx.x >> 2;
    const int n_cta = blockIdx.x & 3;
    const int grp = wid >> 2;              // K-half group
    const int wl  = wid & 3;
    const int wm  = wl >> 1;
    const int wn  = wl & 1;
    const int mt0 = m_cta * 4 + wm * 2;
    const int n16b = n_cta * 4 + wn * 2;   // warp's two n16 blocks

    const uint4* WP0v = (const uint4*)g_WP0;
    const uint4* WP1v = (const uint4*)g_WP1;
    const uint4* XPv  = (const uint4*)g_XP;
    const uint4* HBv  = (const uint4*)g_HB;
    float* gout0 = gsm + grp * 4096;          // L1(t-1) partials
    float* gout1 = gsm + 8192 + grp * 4096;   // L0(t)   partials

    for (int t = 0; t <= 512; t++) {
        const int u = t & 1, v = u ^ 1;
        const bool do1 = (t >= 1);
        const bool do0 = (t <= 511);

        if (do1) {
            // L1(t-1): q0-31 = h0(t-1)@(v,0), q32-63 = h1(t-2)@(u,1)
            float acc[2][4][4] = {};
            const uint4* A0 = WP1v + (mt0 * NQ1) * 64 + lane * 2;
            const uint4* A1 = WP1v + ((mt0 + 1) * NQ1) * 64 + lane * 2;
            if (grp == 0) {
                gemm_seg<32>(A0, A1,
                             HBv + (((v * 2 + 0) * 32) * 16 + n16b) * 32 + lane, acc);
            } else {
                gemm_seg<32>(A0 + 32 * 64, A1 + 32 * 64,
                             HBv + (((u * 2 + 1) * 32) * 16 + n16b) * 32 + lane, acc);
            }
            store_partials(acc, gout0, wm, wn, lane);
        }
        if (do0) {
            // L0(t): q0-31 = h0(t-1)@(v,0), q32-35 = x(t)
            float acc[2][4][4] = {};
            const uint4* A0 = WP0v + (mt0 * NQ0) * 64 + lane * 2;
            const uint4* A1 = WP0v + ((mt0 + 1) * NQ0) * 64 + lane * 2;
            const uint4* Bh = HBv + (((v * 2 + 0) * 32) * 16 + n16b) * 32 + lane;
            if (grp == 0) {
                gemm_seg<18>(A0, A1, Bh, acc);
            } else {
                gemm_seg<14>(A0 + 18 * 64, A1 + 18 * 64, Bh + 18 * 512, acc);
                gemm_seg<4>(A0 + 32 * 64, A1 + 32 * 64,
                            XPv + ((t * 4) * 16 + n16b) * 32 + lane, acc);
            }
            store_partials(acc, gout1, wm, wn, lane);
        }
        __syncthreads();

        if (do1) cell_upd(gsm,        1, v, m_cta, n_cta, tid, t == 512);
        if (do0) cell_upd(gsm + 8192, 0, u, m_cta, n_cta, tid, false);

        grid_barrier();
    }

    // ======== head ========
    if (blockIdx.x == 0) {
        int b = tid;
        float a = __ldg(bout);
#pragma unroll 8
        for (int j = 0; j < 512; j++)
            a += fmaxf(__ldcg(g_h1fin + j * 256 + b), 0.f) * __ldg(Wout + j);
        out[b] = a;
    }
}

// ---------------- launch ----------------------------------------------------
extern "C" void kernel_launch(void* const* d_in, const int* in_sizes, int n_in,
                              void* d_out, int out_size) {
    (void)in_sizes; (void)n_in; (void)out_size;
    const float* x    = (const float*)d_in[0];
    const float* Wih0 = (const float*)d_in[1];
    const float* Whh0 = (const float*)d_in[2];
    const float* bih0 = (const float*)d_in[3];
    const float* bhh0 = (const float*)d_in[4];
    const float* Wih1 = (const float*)d_in[5];
    const float* Whh1 = (const float*)d_in[6];
    const float* bih1 = (const float*)d_in[7];
    const float* bhh1 = (const float*)d_in[8];
    const float* Wout = (const float*)d_in[9];
    const float* bout = (const float*)d_in[10];
    float* out = (float*)d_out;

    cudaFuncSetAttribute(lstm_all, cudaFuncAttributeMaxDynamicSharedMemorySize, SMEM_DYN);
    lstm_all<<<NCTA, NTHR, SMEM_DYN>>>(x, Wih0, Whh0, bih0, bhh0,
                                       Wih1, Whh1, bih1, bhh1, Wout, bout, out);
}

// round 15
// speedup vs baseline: 1.5826x; 1.0306x over previous
#include <cuda_runtime.h>
#include <cuda_fp16.h>

// ============================================================================
// 2-layer LSTM (B=256, T=512, I=64, H=512) + head on sm_100 base via
// mma.sync.m16n8k16 fp16, 2-term A split (exact to 2^-24), B single fp16,
// fp32 accum. 128 persistent CTAs x 256 thr, merged phases (513 barriers).
// R14: (a) warp tile m32 x n64 -- 8 warps = 2 m-slots x 4 K-quarters; per q
// a warp does 8 LDG for 32 HMMA (loads/HMMA 0.375 -> 0.25, total LDG/phase
// 2400 -> 1600). Partials 2x4x16KB smem, cell update sums 4. (b) All h/C
// communication is within the 32 CTAs sharing n_cta -> 4 independent 32-CTA
// barriers instead of one 128-CTA barrier; one global barrier before head.
// ============================================================================

typedef unsigned u32;

#define NCTA 128
#define NTHR 256
#define NQ0  36     // layer-0 k16 tiles: 32 (h0) + 4 (x)
#define NQ1  64     // layer-1 k16 tiles: 32 (h0 cur) + 32 (h1 prev)
#define SMEM_DYN (32768 * 4)   // 2 outputs x 4 K-groups x 64x64 fp32 = 128KB

// ---------------- device scratch (static) -----------------------------------
__device__ __align__(16) __half g_WP0[128 * NQ0 * 512];
__device__ __align__(16) __half g_WP1[128 * NQ1 * 512];
__device__ __align__(16) __half g_XP[512 * 4 * 16 * 256];
__device__ __align__(16) __half g_HB[2 * 2 * 32 * 16 * 256];
__device__ float g_C[2 * 512 * 256];
__device__ float g_h1fin[512 * 256];
__device__ float g_bias[2 * 2048];
__device__ u32 g_barCnt[5];
__device__ volatile u32 g_barGen[5];

// ---------------- helpers ---------------------------------------------------
// Barrier over `cnt` CTAs using slot `idx` (0-3: n-groups of 32; 4: global).
__device__ __forceinline__ void group_barrier(int idx, u32 cnt) {
    __syncthreads();
    if (threadIdx.x == 0) {
        u32 gen = g_barGen[idx];
        __threadfence();
        if (atomicAdd(&g_barCnt[idx], 1u) == cnt - 1u) {
            g_barCnt[idx] = 0u;
            __threadfence();
            g_barGen[idx] = gen + 1u;
        } else {
            while (g_barGen[idx] == gen) { }
        }
        __threadfence();
    }
    __syncthreads();
}

__device__ __forceinline__ float sigm(float x) { return 1.0f / (1.0f + expf(-x)); }

__device__ __forceinline__ void mma4(float* d, uint4 a, u32 b0, u32 b1) {
    asm volatile(
        "mma.sync.aligned.m16n8k16.row.col.f32.f16.f16.f32 "
        "{%0,%1,%2,%3}, {%4,%5,%6,%7}, {%8,%9}, {%0,%1,%2,%3};"
        : "+f"(d[0]), "+f"(d[1]), "+f"(d[2]), "+f"(d[3])
        : "r"(a.x), "r"(a.y), "r"(a.z), "r"(a.w), "r"(b0), "r"(b1));
}

// One contiguous K segment of NQ k16-steps for an m32 x n64 warp tile.
// A0p/A1p: lane-adjusted A block ptrs for two m16 tiles (+64 uint4/q).
// Bp: lane-adjusted B ptr; warp's four n16 blocks at +0,+32,+64,+96
// (+512 uint4 per q). 2-term x 2m x 8n8 = 32 HMMA per q, 8 LDG.128.
template <int NQ>
__device__ __forceinline__ void gemm_seg(
    const uint4* __restrict__ A0p, const uint4* __restrict__ A1p,
    const uint4* __restrict__ Bp, float acc[2][8][4])
{
#pragma unroll 2
    for (int q = 0; q < NQ; q++) {
        uint4 b0  = __ldcg(Bp);
        uint4 b1  = __ldcg(Bp + 32);
        uint4 b2  = __ldcg(Bp + 64);
        uint4 b3  = __ldcg(Bp + 96);
        uint4 ah0 = __ldg(A0p);  uint4 al0 = __ldg(A0p + 1);
        uint4 ah1 = __ldg(A1p);  uint4 al1 = __ldg(A1p + 1);
        mma4(acc[0][0], ah0, b0.x, b0.y);
        mma4(acc[0][0], al0, b0.x, b0.y);
        mma4(acc[0][1], ah0, b0.z, b0.w);
        mma4(acc[0][1], al0, b0.z, b0.w);
        mma4(acc[0][2], ah0, b1.x, b1.y);
        mma4(acc[0][2], al0, b1.x, b1.y);
        mma4(acc[0][3], ah0, b1.z, b1.w);
        mma4(acc[0][3], al0, b1.z, b1.w);
        mma4(acc[0][4], ah0, b2.x, b2.y);
        mma4(acc[0][4], al0, b2.x, b2.y);
        mma4(acc[0][5], ah0, b2.z, b2.w);
        mma4(acc[0][5], al0, b2.z, b2.w);
        mma4(acc[0][6], ah0, b3.x, b3.y);
        mma4(acc[0][6], al0, b3.x, b3.y);
        mma4(acc[0][7], ah0, b3.z, b3.w);
        mma4(acc[0][7], al0, b3.z, b3.w);
        mma4(acc[1][0], ah1, b0.x, b0.y);
        mma4(acc[1][0], al1, b0.x, b0.y);
        mma4(acc[1][1], ah1, b0.z, b0.w);
        mma4(acc[1][1], al1, b0.z, b0.w);
        mma4(acc[1][2], ah1, b1.x, b1.y);
        mma4(acc[1][2], al1, b1.x, b1.y);
        mma4(acc[1][3], ah1, b1.z, b1.w);
        mma4(acc[1][3], al1, b1.z, b1.w);
        mma4(acc[1][4], ah1, b2.x, b2.y);
        mma4(acc[1][4], al1, b2.x, b2.y);
        mma4(acc[1][5], ah1, b2.z, b2.w);
        mma4(acc[1][5], al1, b2.z, b2.w);
        mma4(acc[1][6], ah1, b3.x, b3.y);
        mma4(acc[1][6], al1, b3.x, b3.y);
        mma4(acc[1][7], ah1, b3.z, b3.w);
        mma4(acc[1][7], al1, b3.z, b3.w);
        A0p += 64; A1p += 64; Bp += 512;
    }
}

// Store one warp's partial D tile (m32 x n64) into a gsm region.
__device__ __forceinline__ void store_partials(
    float acc[2][8][4], float* gout, int wm, int lane)
{
#pragma unroll
    for (int mi = 0; mi < 2; mi++)
#pragma unroll
        for (int ni = 0; ni < 8; ni++) {
            int lr = (wm * 2 + mi) * 16 + (lane >> 2);
            int cl = ni * 8 + (lane & 3) * 2;
            float* d = acc[mi][ni];
            *(float2*)&gout[lr * 64 + cl]       = make_float2(d[0], d[1]);
            *(float2*)&gout[(lr + 8) * 64 + cl] = make_float2(d[2], d[3]);
        }
}

// Cell update for one layer; sums FOUR K-group partials (stride 4096).
__device__ __forceinline__ void cell_upd(
    const float* gbase, int lay, int pwv, int m_cta, int n_cta,
    int tid, bool fin)
{
    float* Cp = g_C + lay * 131072;
    const float* bp = g_bias + lay * 2048;
#pragma unroll
    for (int e = 0; e < 4; e++) {
        int cell = e * NTHR + tid;
        int jl = cell >> 6, bl = cell & 63;
        int j = m_cta * 16 + jl;
        int b = n_cta * 64 + bl;
        float g4[4];
#pragma unroll
        for (int gi = 0; gi < 4; gi++) {
            int o = (jl * 4 + gi) * 64 + bl;
            g4[gi] = gbase[o] + gbase[4096 + o] + gbase[8192 + o] + gbase[12288 + o]
                   + __ldg(bp + gi * 512 + j);
        }
        float c = Cp[j * 256 + b];
        c = sigm(g4[1]) * c + sigm(g4[0]) * tanhf(g4[2]);
        Cp[j * 256 + b] = c;
        float hv = sigm(g4[3]) * tanhf(c);
        // fp16 B-fragment scatter: q = m_cta, kl = jl
        int r  = jl >> 3, tg = (jl >> 1) & 3, hb = jl & 1;
        int nl = bl & 7;
        int n8 = n_cta * 8 + (bl >> 3);
        int p  = n8 & 1, n16 = n8 >> 1;
        int l2 = nl * 4 + tg;
        int blk = ((pwv * 2 + lay) * 32 + m_cta) * 16 + n16;
        g_HB[blk * 256 + l2 * 8 + p * 4 + r * 2 + hb] = __float2half(hv);
        if (fin) g_h1fin[j * 256 + b] = hv;
    }
}

// ---------------- the persistent kernel -------------------------------------
extern __shared__ __align__(16) float gsm[];   // [out 2][grp 4][64*64]

__global__ void __launch_bounds__(NTHR, 1) lstm_all(
    const float* __restrict__ x,
    const float* __restrict__ Wih0, const float* __restrict__ Whh0,
    const float* __restrict__ bih0, const float* __restrict__ bhh0,
    const float* __restrict__ Wih1, const float* __restrict__ Whh1,
    const float* __restrict__ bih1, const float* __restrict__ bhh1,
    const float* __restrict__ Wout, const float* __restrict__ bout,
    float* __restrict__ out)
{
    const int tid  = threadIdx.x;
    const int wid  = tid >> 5;
    const int lane = tid & 31;
    const int gtid = blockIdx.x * NTHR + tid;
    const int NT   = NCTA * NTHR;

    // ======== prep: identical layouts to R13 winner ========
    for (int i = gtid; i < 128 * NQ0 * 512; i += NT) {
        int bi = i >> 9, off = i & 511;
        int l = off >> 4, rem = off & 15;
        int sect = rem >> 3, r = (rem >> 1) & 3, h = rem & 1;
        int mt = bi / NQ0, q = bi % NQ0;
        int lr = (l >> 2) + (r & 1) * 8;
        int c  = (l & 3) * 2 + h + (r >> 1) * 8;
        int R  = mt * 16 + lr;
        int GR = (R & 3) * 512 + (R >> 2);
        int k  = q * 16 + c;
        float w = (k < 512) ? Whh0[GR * 512 + k] : Wih0[GR * 64 + (k - 512)];
        __half hh = __float2half(w);
        g_WP0[i] = sect ? __float2half(w - __half2float(hh)) : hh;
    }
    for (int i = gtid; i < 128 * NQ1 * 512; i += NT) {
        int bi = i >> 9, off = i & 511;
        int l = off >> 4, rem = off & 15;
        int sect = rem >> 3, r = (rem >> 1) & 3, h = rem & 1;
        int mt = bi / NQ1, q = bi % NQ1;
        int lr = (l >> 2) + (r & 1) * 8;
        int c  = (l & 3) * 2 + h + (r >> 1) * 8;
        int R  = mt * 16 + lr;
        int GR = (R & 3) * 512 + (R >> 2);
        int k  = q * 16 + c;
        float w = (k < 512) ? Wih1[GR * 512 + k] : Whh1[GR * 512 + (k - 512)];
        __half hh = __float2half(w);
        g_WP1[i] = sect ? __float2half(w - __half2float(hh)) : hh;
    }
    for (int i = gtid; i < 512 * 4 * 16 * 256; i += NT) {
        int bi = i >> 8, off = i & 255;
        int l = off >> 3, rem = off & 7;
        int p = rem >> 2, r = (rem >> 1) & 1, h = rem & 1;
        int n16 = bi & 15, rest = bi >> 4;
        int qp = rest & 3, t = rest >> 2;
        int n8 = n16 * 2 + p;
        int b  = n8 * 8 + (l >> 2);
        int kk = r * 8 + (l & 3) * 2 + h;
        int ii = qp * 16 + kk;
        g_XP[i] = __float2half(x[(b * 512 + t) * 64 + ii]);
    }
    for (int i = gtid; i < 2 * 2 * 32 * 16 * 256; i += NT)
        g_HB[i] = __float2half(0.f);
    for (int i = gtid; i < 2 * 512 * 256; i += NT) g_C[i] = 0.f;
    for (int i = gtid; i < 2048; i += NT) {
        g_bias[i]        = bih0[i] + bhh0[i];
        g_bias[2048 + i] = bih1[i] + bhh1[i];
    }

    group_barrier(4, NCTA);   // global: prep visible everywhere

    // ======== merged mainloop: phase t = { L1(t-1), L0(t) } ========
    const int m_cta = blockIdx.x >> 2;
    const int n_cta = blockIdx.x & 3;
    const int grp = wid >> 1;              // K-quarter group, 0..3
    const int wm  = wid & 1;               // m-slot (m32)
    const int mt0 = m_cta * 4 + wm * 2;
    const int n16b = n_cta * 4;            // warp covers all 4 n16 blocks

    const uint4* WP0v = (const uint4*)g_WP0;
    const uint4* WP1v = (const uint4*)g_WP1;
    const uint4* XPv  = (const uint4*)g_XP;
    const uint4* HBv  = (const uint4*)g_HB;
    float* gout0 = gsm + grp * 4096;           // L1(t-1) partials
    float* gout1 = gsm + 16384 + grp * 4096;   // L0(t)   partials

    for (int t = 0; t <= 512; t++) {
        const int u = t & 1, v = u ^ 1;
        const bool do1 = (t >= 1);
        const bool do0 = (t <= 511);

        if (do1) {
            // L1(t-1): q0-31 = h0(t-1)@(v,0), q32-63 = h1(t-2)@(u,1)
            float acc[2][8][4] = {};
            const uint4* A0 = WP1v + (mt0 * NQ1) * 64 + lane * 2;
            const uint4* A1 = WP1v + ((mt0 + 1) * NQ1) * 64 + lane * 2;
            const uint4* B0 = HBv + (((v * 2 + 0) * 32) * 16 + n16b) * 32 + lane;
            const uint4* B1 = HBv + (((u * 2 + 1) * 32) * 16 + n16b) * 32 + lane;
            if (grp == 0)      gemm_seg<16>(A0,           A1,           B0, acc);
            else if (grp == 1) gemm_seg<16>(A0 + 16 * 64, A1 + 16 * 64, B0 + 16 * 512, acc);
            else if (grp == 2) gemm_seg<16>(A0 + 32 * 64, A1 + 32 * 64, B1, acc);
            else               gemm_seg<16>(A0 + 48 * 64, A1 + 48 * 64, B1 + 16 * 512, acc);
            store_partials(acc, gout0, wm, lane);
        }
        if (do0) {
            // L0(t): q0-31 = h0(t-1)@(v,0), q32-35 = x(t)
            float acc[2][8][4] = {};
            const uint4* A0 = WP0v + (mt0 * NQ0) * 64 + lane * 2;
            const uint4* A1 = WP0v + ((mt0 + 1) * NQ0) * 64 + lane * 2;
            const uint4* Bh = HBv + (((v * 2 + 0) * 32) * 16 + n16b) * 32 + lane;
            if (grp == 0)      gemm_seg<10>(A0,           A1,           Bh, acc);
            else if (grp == 1) gemm_seg<10>(A0 + 10 * 64, A1 + 10 * 64, Bh + 10 * 512, acc);
            else if (grp == 2) gemm_seg<10>(A0 + 20 * 64, A1 + 20 * 64, Bh + 20 * 512, acc);
            else {
                gemm_seg<2>(A0 + 30 * 64, A1 + 30 * 64, Bh + 30 * 512, acc);
                gemm_seg<4>(A0 + 32 * 64, A1 + 32 * 64,
                            XPv + ((t * 4) * 16 + n16b) * 32 + lane, acc);
            }
            store_partials(acc, gout1, wm, lane);
        }
        __syncthreads();

        if (do1) cell_upd(gsm,         1, v, m_cta, n_cta, tid, t == 512);
        if (do0) cell_upd(gsm + 16384, 0, u, m_cta, n_cta, tid, false);

        // all h/C exchange stays within this n-group of 32 CTAs
        group_barrier(n_cta, 32);
    }

    group_barrier(4, NCTA);   // global: h1fin complete before head

    // ======== head ========
    if (blockIdx.x == 0) {
        int b = tid;
        float a = __ldg(bout);
#pragma unroll 8
        for (int j = 0; j < 512; j++)
            a += fmaxf(__ldcg(g_h1fin + j * 256 + b), 0.f) * __ldg(Wout + j);
        out[b] = a;
    }
}

// ---------------- launch ----------------------------------------------------
extern "C" void kernel_launch(void* const* d_in, const int* in_sizes, int n_in,
                              void* d_out, int out_size) {
    (void)in_sizes; (void)n_in; (void)out_size;
    const float* x    = (const float*)d_in[0];
    const float* Wih0 = (const float*)d_in[1];
    const float* Whh0 = (const float*)d_in[2];
    const float* bih0 = (const float*)d_in[3];
    const float* bhh0 = (const float*)d_in[4];
    const float* Wih1 = (const float*)d_in[5];
    const float* Whh1 = (const float*)d_in[6];
    const float* bih1 = (const float*)d_in[7];
    const float* bhh1 = (const float*)d_in[8];
    const float* Wout = (const float*)d_in[9];
    const float* bout = (const float*)d_in[10];
    float* out = (float*)d_out;

    cudaFuncSetAttribute(lstm_all, cudaFuncAttributeMaxDynamicSharedMemorySize, SMEM_DYN);
    lstm_all<<<NCTA, NTHR, SMEM_DYN>>>(x, Wih0, Whh0, bih0, bhh0,
                                       Wih1, Whh1, bih1, bhh1, Wout, bout, out);
}